// round 5
// baseline (speedup 1.0000x reference)
#include <cuda_runtime.h>
#include <cstdint>
#include <cfloat>

#define NPTS   8192
#define BMAX   8
#define G      24
#define GM     (G - 1)
#define NCELLS (G * G * G)            // 13824
#define NSB    (2 * BMAX)
#define T      64                     // threads per query block
#define MAXQ   4                      // queries per thread per wave
#define CAP    1536                   // smem candidate buffer (float4)
#define NBLK   2048                   // query blocks

typedef unsigned int uint;

// ---- scratch (device globals; no allocation) --------------------------------
__device__ float4 g_sorted[NSB * NPTS];
__device__ int    g_hist[NSB * NCELLS];
__device__ int    g_cellstart[NSB * (NCELLS + 1)];
__device__ int    g_offsets[NSB * NCELLS];
__device__ uint   g_bboxEnc[NSB * 6];
__device__ float  g_bboxDec[NSB * 10];     // o[3], w[3], inv[3], pad
__device__ float  g_part[NBLK];

__device__ __forceinline__ uint fenc(float f) {
    uint u = __float_as_uint(f);
    return (u & 0x80000000u) ? ~u : (u | 0x80000000u);
}
__device__ __forceinline__ float fdec(uint u) {
    return __uint_as_float((u & 0x80000000u) ? (u ^ 0x80000000u) : ~u);
}
__device__ __forceinline__ int cell_clamp(float v, float o, float inv) {
    int c = (int)floorf((v - o) * inv);
    return min(GM, max(0, c));
}
__device__ __forceinline__ const float* set_base(const float* preds,
                                                 const float* gts, int sb, int B) {
    int set = sb / B, b = sb - set * B;
    return (set == 0 ? preds : gts) + (size_t)b * 3 * NPTS;
}

// ==== K0: init bbox atomics ===================================================
__global__ void k0_init() {
    int t = threadIdx.x;
    if (t < NSB * 6) g_bboxEnc[t] = ((t % 6) < 3) ? 0xFFFFFFFFu : 0u;
}

// ==== K1: zero hist slice + bbox min/max (wide) ===============================
__global__ void k1_bbox_zero(const float* __restrict__ preds,
                             const float* __restrict__ gts, int B) {
    const int sb = blockIdx.x, chunk = blockIdx.y, t = threadIdx.x;
    const float* P = set_base(preds, gts, sb, B);

    // zero hist slice
    int* hist = g_hist + (size_t)sb * NCELLS;
    const int ZC = (NCELLS + 3) / 4;
    for (int i = chunk * ZC + t; i < min((chunk + 1) * ZC, NCELLS); i += 256)
        hist[i] = 0;

    const int CH = NPTS / 4, start = chunk * CH;
    float lmn[3] = {FLT_MAX, FLT_MAX, FLT_MAX};
    float lmx[3] = {-FLT_MAX, -FLT_MAX, -FLT_MAX};
#pragma unroll
    for (int a = 0; a < 3; a++)
        for (int i = start + t; i < start + CH; i += 256) {
            float v = P[a * NPTS + i];
            lmn[a] = fminf(lmn[a], v);
            lmx[a] = fmaxf(lmx[a], v);
        }
#pragma unroll
    for (int o = 16; o > 0; o >>= 1)
#pragma unroll
        for (int a = 0; a < 3; a++) {
            lmn[a] = fminf(lmn[a], __shfl_xor_sync(0xffffffffu, lmn[a], o));
            lmx[a] = fmaxf(lmx[a], __shfl_xor_sync(0xffffffffu, lmx[a], o));
        }
    if ((t & 31) == 0)
#pragma unroll
        for (int a = 0; a < 3; a++) {
            atomicMin(&g_bboxEnc[sb * 6 + a],     fenc(lmn[a]));
            atomicMax(&g_bboxEnc[sb * 6 + 3 + a], fenc(lmx[a]));
        }
}

// ==== K2: decode bbox + histogram (wide) ======================================
__global__ void k2_hist(const float* __restrict__ preds,
                        const float* __restrict__ gts, int B) {
    const int sb = blockIdx.x, chunk = blockIdx.y, t = threadIdx.x;
    const float* P = set_base(preds, gts, sb, B);
    __shared__ float bb[10];
    if (t == 0) {
#pragma unroll
        for (int a = 0; a < 3; a++) {
            float mn = fdec(g_bboxEnc[sb * 6 + a]);
            float mx = fdec(g_bboxEnc[sb * 6 + 3 + a]);
            float w  = fmaxf(mx - mn, 1e-5f) * (1.0f / G);
            bb[a] = mn; bb[3 + a] = w; bb[6 + a] = 1.0f / w;
        }
        if (chunk == 0)
#pragma unroll
            for (int k = 0; k < 9; k++) g_bboxDec[sb * 10 + k] = bb[k];
    }
    __syncthreads();
    int* hist = g_hist + (size_t)sb * NCELLS;
    const int CH = NPTS / 4, start = chunk * CH;
    for (int i = start + t; i < start + CH; i += 256) {
        int cx = cell_clamp(P[i],            bb[0], bb[6]);
        int cy = cell_clamp(P[NPTS + i],     bb[1], bb[7]);
        int cz = cell_clamp(P[2 * NPTS + i], bb[2], bb[8]);
        atomicAdd(&hist[(cz * G + cy) * G + cx], 1);
    }
}

// ==== K3: per-sb exclusive scan ===============================================
__global__ void k3_scan(int B) {
    const int sb = blockIdx.x, t = threadIdx.x;
    const int* hist = g_hist + (size_t)sb * NCELLS;
    int* cs   = g_cellstart + (size_t)sb * (NCELLS + 1);
    int* offs = g_offsets + (size_t)sb * NCELLS;
    __shared__ int ssum[256];
    const int CPT = NCELLS / 256;  // 54
    const int first = t * CPT;
    int local = 0;
#pragma unroll 8
    for (int i = 0; i < CPT; i++) local += hist[first + i];
    ssum[t] = local;
    __syncthreads();
    for (int off = 1; off < 256; off <<= 1) {
        int v = (t >= off) ? ssum[t - off] : 0;
        __syncthreads();
        ssum[t] += v;
        __syncthreads();
    }
    int run = ssum[t] - local;
    for (int i = 0; i < CPT; i++) {
        int c = first + i;
        cs[c] = run;
        offs[c] = run;
        run += hist[c];
    }
    if (t == 255) cs[NCELLS] = run;
}

// ==== K4: scatter (wide) ======================================================
__global__ void k4_scatter(const float* __restrict__ preds,
                           const float* __restrict__ gts, int B) {
    const int sb = blockIdx.x, chunk = blockIdx.y, t = threadIdx.x;
    const float* P = set_base(preds, gts, sb, B);
    __shared__ float bb[10];
    if (t < 9) bb[t] = g_bboxDec[sb * 10 + t];
    __syncthreads();
    int* offs = g_offsets + (size_t)sb * NCELLS;
    float4* dst = g_sorted + (size_t)sb * NPTS;
    const int CH = NPTS / 4, start = chunk * CH;
    for (int i = start + t; i < start + CH; i += 256) {
        float x = P[i], y = P[NPTS + i], z = P[2 * NPTS + i];
        int cx = cell_clamp(x, bb[0], bb[6]);
        int cy = cell_clamp(y, bb[1], bb[7]);
        int cz = cell_clamp(z, bb[2], bb[8]);
        int pos = atomicAdd(&offs[(cz * G + cy) * G + cx], 1);
        dst[pos] = make_float4(x, y, z, x * x + y * y + z * z);
    }
}

// ==== K5: cell-cooperative exact NN ===========================================
__global__ __launch_bounds__(T)
void k5_query(int B) {
    __shared__ float4 sbuf[CAP];
    __shared__ float  sred[T];
    __shared__ int    sflag[64];
    __shared__ float  sqb[9], srb[9];
    __shared__ int    sdone;

    const int t = threadIdx.x;
    float acc = 0.f;  // meaningful on t==0 only

    const int total  = 2 * B * NCELLS;
    const int nchunk = (total + 63) / 64;

    for (int ch = blockIdx.x; ch < nchunk; ch += gridDim.x) {
        const int base = ch * 64;
        __syncthreads();
        {   // occupancy flags for the next 64 cells
            int idx = base + t;
            int f = 0;
            if (idx < total) {
                int sb = idx / NCELLS, cell = idx - sb * NCELLS;
                const int* qcs = g_cellstart + (size_t)sb * (NCELLS + 1);
                f = (__ldg(qcs + cell + 1) - __ldg(qcs + cell)) > 0;
            }
            sflag[t] = f;
        }
        __syncthreads();

        for (int e = 0; e < 64 && base + e < total; e++) {
            if (!sflag[e]) continue;  // block-uniform
            const int idx  = base + e;
            const int sb   = idx / NCELLS;
            const int cell = idx - sb * NCELLS;
            const int set  = sb / B;
            const int sbr  = (1 - set) * B + (sb - set * B);

            if (t < 9)       sqb[t]     = g_bboxDec[sb  * 10 + t];
            else if (t < 18) srb[t - 9] = g_bboxDec[sbr * 10 + (t - 9)];
            __syncthreads();

            const int* qcs = g_cellstart + (size_t)sb  * (NCELLS + 1);
            const int* rcs = g_cellstart + (size_t)sbr * (NCELLS + 1);
            const float4* qpts = g_sorted + (size_t)sb  * NPTS;
            const float4* rpts = g_sorted + (size_t)sbr * NPTS;

            const int qbeg = __ldg(qcs + cell), qend = __ldg(qcs + cell + 1);
            const int nq = qend - qbeg;

            // query cell spatial box -> ref-grid base box
            const int cqx = cell % G, cqy = (cell / G) % G, cqz = cell / (G * G);
            const float qx0 = sqb[0] + cqx * sqb[3], qx1 = qx0 + sqb[3];
            const float qy0 = sqb[1] + cqy * sqb[4], qy1 = qy0 + sqb[4];
            const float qz0 = sqb[2] + cqz * sqb[5], qz1 = qz0 + sqb[5];
            const int bxlo = cell_clamp(qx0, srb[0], srb[6]);
            const int bxhi = cell_clamp(qx1, srb[0], srb[6]);
            const int bylo = cell_clamp(qy0, srb[1], srb[7]);
            const int byhi = cell_clamp(qy1, srb[1], srb[7]);
            const int bzlo = cell_clamp(qz0, srb[2], srb[8]);
            const int bzhi = cell_clamp(qz1, srb[2], srb[8]);

            const int nwaves = (nq + T * MAXQ - 1) / (T * MAXQ);
            float tsum = 0.f;

            for (int qw = 0; qw < nwaves; qw++) {
                const int qoff = qbeg + qw * T * MAXQ;
                const int qcount = min(nq - qw * T * MAXQ, T * MAXQ);
                const int KQ = (qcount + T - 1) / T;  // block-uniform

                float px[MAXQ], py[MAXQ], pz[MAXQ], pr[MAXQ], mb[MAXQ];
#pragma unroll
                for (int k = 0; k < MAXQ; k++) {
                    px[k] = py[k] = pz[k] = pr[k] = 0.f;
                    mb[k] = FLT_MAX;
                    if (k < KQ) {
                        int li = k * T + t;
                        if (li < qcount) {
                            float4 p = __ldg(qpts + qoff + li);
                            px[k] = p.x; py[k] = p.y; pz[k] = p.z; pr[k] = p.w;
                        }
                    }
                }

                int xlo = bxlo, xhi = bxhi, ylo = bylo, yhi = byhi,
                    zlo = bzlo, zhi = bzhi;
                int fill = 0;

                for (int r = 0; ; r++) {
                    int pxl = xlo, pxh = xhi, pyl = ylo, pyh = yhi,
                        pzl = zlo, pzh = zhi;
                    if (r > 0) {
                        xlo = max(xlo - 1, 0); xhi = min(xhi + 1, GM);
                        ylo = max(ylo - 1, 0); yhi = min(yhi + 1, GM);
                        zlo = max(zlo - 1, 0); zhi = min(zhi + 1, GM);
                        if (xlo == pxl && xhi == pxh && ylo == pyl &&
                            yhi == pyh && zlo == pzl && zhi == pzh)
                            break;  // box static and not done -> covered grid
                    }
                    // stage ring rows (block-uniform)
                    for (int z = zlo; z <= zhi; z++) {
                        bool zin = (r > 0) && (z >= pzl) && (z <= pzh);
                        for (int y = ylo; y <= yhi; y++) {
                            bool yin = (r > 0) && (y >= pyl) && (y <= pyh);
                            int row = (z * G + y) * G;
                            int c0, c1;
                            for (int seg = 0; seg < 2; seg++) {
                                if (r == 0 || !(zin && yin)) {
                                    if (seg == 1) break;
                                    c0 = row + xlo; c1 = row + xhi;
                                } else {
                                    if (seg == 0) { if (xlo >= pxl) continue; c0 = row + xlo; c1 = row + pxl - 1; }
                                    else          { if (xhi <= pxh) continue; c0 = row + pxh + 1; c1 = row + xhi; }
                                }
                                int beg = __ldg(rcs + c0);
                                int end = __ldg(rcs + c1 + 1);
                                while (beg < end) {
                                    int take = min(end - beg, CAP - fill);
                                    for (int i = t; i < take; i += T)
                                        sbuf[fill + i] = __ldg(rpts + beg + i);
                                    fill += take; beg += take;
                                    if (fill == CAP) {
                                        __syncthreads();
#pragma unroll 2
                                        for (int c = 0; c < CAP; c++) {
                                            float4 p = sbuf[c];
#pragma unroll
                                            for (int k = 0; k < MAXQ; k++)
                                                if (k < KQ) {
                                                    float dot = fmaf(px[k], p.x, fmaf(py[k], p.y, pz[k] * p.z));
                                                    mb[k] = fminf(mb[k], fmaf(-2.f, dot, p.w));
                                                }
                                        }
                                        __syncthreads();
                                        fill = 0;
                                    }
                                }
                            }
                        }
                    }
                    // flush remainder
                    __syncthreads();
#pragma unroll 2
                    for (int c = 0; c < fill; c++) {
                        float4 p = sbuf[c];
#pragma unroll
                        for (int k = 0; k < MAXQ; k++)
                            if (k < KQ) {
                                float dot = fmaf(px[k], p.x, fmaf(py[k], p.y, pz[k] * p.z));
                                mb[k] = fminf(mb[k], fmaf(-2.f, dot, p.w));
                            }
                    }
                    __syncthreads();
                    fill = 0;

                    // termination: per-query inner face gap vs best distance
                    if (t == 0) sdone = 1;
                    __syncthreads();
                    {
                        float BX0 = srb[0] + xlo * srb[3], BX1 = srb[0] + (xhi + 1) * srb[3];
                        float BY0 = srb[1] + ylo * srb[4], BY1 = srb[1] + (yhi + 1) * srb[4];
                        float BZ0 = srb[2] + zlo * srb[5], BZ1 = srb[2] + (zhi + 1) * srb[5];
                        bool mydone = true;
#pragma unroll
                        for (int k = 0; k < MAXQ; k++) {
                            if (k >= KQ) break;
                            int li = k * T + t;
                            if (li >= qcount) break;
                            float gx = fminf(xlo > 0  ? (px[k] - BX0) : FLT_MAX,
                                             xhi < GM ? (BX1 - px[k]) : FLT_MAX);
                            float gy = fminf(ylo > 0  ? (py[k] - BY0) : FLT_MAX,
                                             yhi < GM ? (BY1 - py[k]) : FLT_MAX);
                            float gz = fminf(zlo > 0  ? (pz[k] - BZ0) : FLT_MAX,
                                             zhi < GM ? (BZ1 - pz[k]) : FLT_MAX);
                            float gap = fminf(gx, fminf(gy, gz));
                            float bd = mb[k] + pr[k];
                            bool dk = (bd <= 0.f) ||
                                      (gap >= 3.4e37f) ||
                                      (gap > 0.f && gap * gap >= bd);
                            mydone = mydone && dk;
                        }
                        if (!mydone) sdone = 0;
                    }
                    __syncthreads();
                    if (sdone) break;
                }

#pragma unroll
                for (int k = 0; k < MAXQ; k++) {
                    if (k >= KQ) break;
                    int li = k * T + t;
                    if (li < qcount) tsum += mb[k] + pr[k];
                }
            }

            // block tree reduction of this cell's sum
            sred[t] = tsum;
            __syncthreads();
            for (int s = T / 2; s > 0; s >>= 1) {
                if (t < s) sred[t] += sred[t + s];
                __syncthreads();
            }
            if (t == 0) acc += sred[0];
            __syncthreads();
        }
    }
    if (t == 0) g_part[blockIdx.x] = acc;
}

// ==== K6: deterministic final sum =============================================
__global__ void k6_final(float* __restrict__ out) {
    __shared__ float sred[256];
    float s = 0.f;
    for (int i = threadIdx.x; i < NBLK; i += 256) s += g_part[i];
    sred[threadIdx.x] = s;
    __syncthreads();
    for (int st = 128; st > 0; st >>= 1) {
        if (threadIdx.x < st) sred[threadIdx.x] += sred[threadIdx.x + st];
        __syncthreads();
    }
    if (threadIdx.x == 0) out[0] = sred[0];
}

extern "C" void kernel_launch(void* const* d_in, const int* in_sizes, int n_in,
                              void* d_out, int out_size) {
    const float* preds = (const float*)d_in[0];
    const float* gts   = (const float*)d_in[1];
    float* out = (float*)d_out;
    const int B = in_sizes[0] / (3 * NPTS);  // 8 here

    k0_init<<<1, 128>>>();
    k1_bbox_zero<<<dim3(2 * B, 4), 256>>>(preds, gts, B);
    k2_hist<<<dim3(2 * B, 4), 256>>>(preds, gts, B);
    k3_scan<<<2 * B, 256>>>(B);
    k4_scatter<<<dim3(2 * B, 4), 256>>>(preds, gts, B);
    k5_query<<<NBLK, T>>>(B);
    k6_final<<<1, 256>>>(out);
}

// round 7
// speedup vs baseline: 2.8825x; 2.8825x over previous
#include <cuda_runtime.h>
#include <cstdint>
#include <cfloat>

#define NPTS 8192
#define BMAX 8
#define NB   256                      // z-buckets per set-batch
#define NSB  (2 * BMAX)
#define QT   256                      // query block threads (= queries/block)
#define EXPB 2                        // buckets per expansion step
#define ZMIN (-6.0f)
#define ZSPAN 12.0f
#define NQBLK (NPTS / QT * BMAX * 2)  // 512 query blocks max

// ---- scratch (device globals; no allocation) --------------------------------
__device__ float4 g_sorted[NSB * NPTS];        // z-bucket-sorted, w = |p|^2
__device__ int    g_cellstart[NSB * (NB + 1)];
__device__ float  g_part[NQBLK];

__device__ __forceinline__ int zbucket(float z) {
    int c = (int)((z - ZMIN) * (NB / ZSPAN));
    return min(NB - 1, max(0, c));
}

// ==== K1: per set-batch: smem hist -> smem scan -> scatter ===================
__global__ __launch_bounds__(256)
void k_prep(const float* __restrict__ preds,
            const float* __restrict__ gts, int B) {
    const int sb  = blockIdx.x;
    const int set = sb / B, b = sb - set * B;
    const float* P = (set == 0 ? preds : gts) + (size_t)b * 3 * NPTS;
    const int t = threadIdx.x;

    __shared__ int s_cnt[NB];
    __shared__ int s_off[NB];

    s_cnt[t] = 0;
    __syncthreads();

    // histogram over z (coalesced loads, smem atomics)
    for (int i = t; i < NPTS; i += 256) {
        float z = P[2 * NPTS + i];
        atomicAdd(&s_cnt[zbucket(z)], 1);
    }
    __syncthreads();

    // inclusive Hillis-Steele scan of s_cnt (256 elements)
    int own = s_cnt[t];
    s_off[t] = own;
    __syncthreads();
    for (int off = 1; off < 256; off <<= 1) {
        int v = (t >= off) ? s_off[t - off] : 0;
        __syncthreads();
        s_off[t] += v;
        __syncthreads();
    }
    int incl = s_off[t];
    int excl = incl - own;

    g_cellstart[sb * (NB + 1) + t] = excl;
    if (t == NB - 1) g_cellstart[sb * (NB + 1) + NB] = incl;  // = NPTS

    // reuse s_cnt as running offsets
    s_cnt[t] = excl;
    __syncthreads();

    float4* dst = g_sorted + (size_t)sb * NPTS;
    for (int i = t; i < NPTS; i += 256) {
        float x = P[i], y = P[NPTS + i], z = P[2 * NPTS + i];
        int pos = atomicAdd(&s_cnt[zbucket(z)], 1);
        dst[pos] = make_float4(x, y, z, x * x + y * y + z * z);
    }
}

// ==== K2: sort-sweep exact NN over contiguous z-window =======================
__global__ __launch_bounds__(QT)
void k_query(int B) {
    const int b   = blockIdx.y;
    const int dir = blockIdx.z;
    const int t   = threadIdx.x;

    const int sbq = (dir == 0 ? 0 : B) + b;   // queries
    const int sbr = (dir == 0 ? B : 0) + b;   // references (other set)

    const int*    cs  = g_cellstart + (size_t)sbr * (NB + 1);
    const float4* rpt = g_sorted + (size_t)sbr * NPTS;

    // my query (queries are z-sorted -> block shares a tight z-range)
    const int qidx = blockIdx.x * QT + t;
    float4 q = __ldg(&g_sorted[(size_t)sbq * NPTS + qidx]);
    const float nx = -2.f * q.x, ny = -2.f * q.y, nz = -2.f * q.z;
    const float rx = q.w, zq = q.z;
    const int myb = zbucket(zq);

    __shared__ int s_lo, s_hi;
    if (t == 0)      s_lo = max(myb - 1, 0);
    if (t == QT - 1) s_hi = min(myb + 1, NB - 1);
    __syncthreads();

    int wlo = s_lo, whi = s_hi;
    float mb = FLT_MAX;

    // evaluate [beg, end) of the sorted ref stream (uniform-address broadcast)
    auto eval = [&](int beg, int end) {
#pragma unroll 4
        for (int k = beg; k < end; k++) {
            float4 p = __ldg(rpt + k);
            float d = fmaf(nx, p.x, fmaf(ny, p.y, fmaf(nz, p.z, p.w)));
            mb = fminf(mb, d);
        }
    };

    eval(__ldg(cs + wlo), __ldg(cs + whi + 1));

    const float W = ZSPAN / NB;
    for (;;) {
        float b2 = mb + rx;                       // best squared distance
        float gl = zq - (ZMIN + wlo * W);         // gap to window's left edge
        float gr = (ZMIN + (whi + 1) * W) - zq;   // gap to right edge
        bool doneL = (wlo == 0)      || (gl * gl >= b2);
        bool doneR = (whi == NB - 1) || (gr * gr >= b2);
        if (__syncthreads_and(doneL && doneR)) break;

        int nlo = max(wlo - EXPB, 0);
        int nhi = min(whi + EXPB, NB - 1);
        if (nlo == wlo && nhi == whi) break;      // whole set covered
        if (nlo < wlo) eval(__ldg(cs + nlo), __ldg(cs + wlo));
        if (nhi > whi) eval(__ldg(cs + whi + 1), __ldg(cs + nhi + 1));
        wlo = nlo; whi = nhi;
    }

    // deterministic-shape block tree reduction
    __shared__ float sred[QT];
    sred[t] = mb + rx;
    __syncthreads();
    for (int s = QT / 2; s > 0; s >>= 1) {
        if (t < s) sred[t] += sred[t + s];
        __syncthreads();
    }
    if (t == 0) {
        int bid = (blockIdx.z * gridDim.y + blockIdx.y) * gridDim.x + blockIdx.x;
        g_part[bid] = sred[0];
    }
}

// ==== K3: fixed-order final sum ==============================================
__global__ void k_final(float* __restrict__ out, int nblk) {
    __shared__ float sred[256];
    float s = 0.f;
    for (int i = threadIdx.x; i < nblk; i += 256) s += g_part[i];
    sred[threadIdx.x] = s;
    __syncthreads();
    for (int st = 128; st > 0; st >>= 1) {
        if (threadIdx.x < st) sred[threadIdx.x] += sred[threadIdx.x + st];
        __syncthreads();
    }
    if (threadIdx.x == 0) out[0] = sred[0];
}

extern "C" void kernel_launch(void* const* d_in, const int* in_sizes, int n_in,
                              void* d_out, int out_size) {
    const float* preds = (const float*)d_in[0];
    const float* gts   = (const float*)d_in[1];
    float* out = (float*)d_out;
    const int B = in_sizes[0] / (3 * NPTS);  // 8 here

    k_prep<<<2 * B, 256>>>(preds, gts, B);
    dim3 grid(NPTS / QT, B, 2);              // (32, 8, 2) = 512 blocks
    k_query<<<grid, QT>>>(B);
    k_final<<<1, 256>>>(out, (NPTS / QT) * B * 2);
}

// round 8
// speedup vs baseline: 6.0222x; 2.0892x over previous
#include <cuda_runtime.h>
#include <cstdint>
#include <cfloat>

#define NPTS 8192
#define BMAX 8
#define NB   256                      // z-buckets per set-batch
#define NSB  (2 * BMAX)
#define QT   256                      // query block threads (= queries/block)
#define EXPB 3                        // buckets per expansion step
#define INITR 3                       // initial window half-extra (buckets)
#define CHUNK 1024                    // smem staging chunk (float4) = 16KB
#define ZMIN (-6.0f)
#define ZSPAN 12.0f
#define NQBLK (NPTS / QT * BMAX * 2)  // 512 query blocks max

// ---- scratch (device globals; no allocation) --------------------------------
__device__ float4 g_sorted[NSB * NPTS];        // z-bucket-sorted, w = |p|^2
__device__ int    g_cellstart[NSB * (NB + 1)];
__device__ float  g_part[NQBLK];

__device__ __forceinline__ int zbucket(float z) {
    int c = (int)((z - ZMIN) * (NB / ZSPAN));
    return min(NB - 1, max(0, c));
}

// ==== K1: per set-batch: smem hist -> smem scan -> scatter ===================
__global__ __launch_bounds__(256)
void k_prep(const float* __restrict__ preds,
            const float* __restrict__ gts, int B) {
    const int sb  = blockIdx.x;
    const int set = sb / B, b = sb - set * B;
    const float* P = (set == 0 ? preds : gts) + (size_t)b * 3 * NPTS;
    const int t = threadIdx.x;

    __shared__ int s_cnt[NB];
    __shared__ int s_off[NB];

    s_cnt[t] = 0;
    __syncthreads();

    for (int i = t; i < NPTS; i += 256) {
        float z = P[2 * NPTS + i];
        atomicAdd(&s_cnt[zbucket(z)], 1);
    }
    __syncthreads();

    int own = s_cnt[t];
    s_off[t] = own;
    __syncthreads();
    for (int off = 1; off < 256; off <<= 1) {
        int v = (t >= off) ? s_off[t - off] : 0;
        __syncthreads();
        s_off[t] += v;
        __syncthreads();
    }
    int incl = s_off[t];
    int excl = incl - own;

    g_cellstart[sb * (NB + 1) + t] = excl;
    if (t == NB - 1) g_cellstart[sb * (NB + 1) + NB] = incl;

    s_cnt[t] = excl;
    __syncthreads();

    float4* dst = g_sorted + (size_t)sb * NPTS;
    for (int i = t; i < NPTS; i += 256) {
        float x = P[i], y = P[NPTS + i], z = P[2 * NPTS + i];
        int pos = atomicAdd(&s_cnt[zbucket(z)], 1);
        dst[pos] = make_float4(x, y, z, x * x + y * y + z * z);
    }
}

// ==== no-op padding so k_query is the 4th launch (ncu profiles launch #4) ====
__global__ void k_nop() {}

// ==== K2: sort-sweep exact NN, smem-staged window ============================
__global__ __launch_bounds__(QT)
void k_query(int B) {
    const int b   = blockIdx.y;
    const int dir = blockIdx.z;
    const int t   = threadIdx.x;

    const int sbq = (dir == 0 ? 0 : B) + b;   // queries
    const int sbr = (dir == 0 ? B : 0) + b;   // references (other set)

    const int*    cs  = g_cellstart + (size_t)sbr * (NB + 1);
    const float4* rpt = g_sorted + (size_t)sbr * NPTS;

    const int qidx = blockIdx.x * QT + t;
    float4 q = __ldg(&g_sorted[(size_t)sbq * NPTS + qidx]);
    const float nx = -2.f * q.x, ny = -2.f * q.y, nz = -2.f * q.z;
    const float rx = q.w, zq = q.z;
    const int myb = zbucket(zq);

    __shared__ float4 sbuf[CHUNK];
    __shared__ int s_lo, s_hi;
    if (t == 0)      s_lo = max(myb - INITR, 0);
    if (t == QT - 1) s_hi = min(myb + INITR, NB - 1);
    __syncthreads();

    int wlo = s_lo, whi = s_hi;
    float mbA = FLT_MAX, mbB = FLT_MAX;

    // block-uniform staged evaluation of ref points [beg, end)
    auto stage_eval = [&](int beg, int end) {
        for (int base = beg; base < end; base += CHUNK) {
            const int take = min(CHUNK, end - base);   // block-uniform
            __syncthreads();
            for (int i = t; i < take; i += QT)
                sbuf[i] = __ldg(rpt + base + i);
            __syncthreads();
            int j = 0;
            for (; j + 8 <= take; j += 8) {
#pragma unroll
                for (int u = 0; u < 8; u += 2) {
                    float4 p  = sbuf[j + u];
                    float4 p2 = sbuf[j + u + 1];
                    mbA = fminf(mbA, fmaf(nx, p.x,  fmaf(ny, p.y,  fmaf(nz, p.z,  p.w))));
                    mbB = fminf(mbB, fmaf(nx, p2.x, fmaf(ny, p2.y, fmaf(nz, p2.z, p2.w))));
                }
            }
            for (; j < take; j++) {
                float4 p = sbuf[j];
                mbA = fminf(mbA, fmaf(nx, p.x, fmaf(ny, p.y, fmaf(nz, p.z, p.w))));
            }
        }
    };

    stage_eval(__ldg(cs + wlo), __ldg(cs + whi + 1));

    const float W = ZSPAN / NB;
    for (;;) {
        float mb = fminf(mbA, mbB);
        float b2 = mb + rx;                       // best squared distance
        float gl = zq - (ZMIN + wlo * W);
        float gr = (ZMIN + (whi + 1) * W) - zq;
        bool doneL = (wlo == 0)      || (gl * gl >= b2);
        bool doneR = (whi == NB - 1) || (gr * gr >= b2);
        if (__syncthreads_and(doneL && doneR)) break;

        int nlo = max(wlo - EXPB, 0);
        int nhi = min(whi + EXPB, NB - 1);
        if (nlo == wlo && nhi == whi) break;      // whole set covered
        if (nlo < wlo) stage_eval(__ldg(cs + nlo), __ldg(cs + wlo));
        if (nhi > whi) stage_eval(__ldg(cs + whi + 1), __ldg(cs + nhi + 1));
        wlo = nlo; whi = nhi;
    }

    // deterministic-shape block tree reduction
    __shared__ float sred[QT];
    sred[t] = fminf(mbA, mbB) + rx;
    __syncthreads();
    for (int s = QT / 2; s > 0; s >>= 1) {
        if (t < s) sred[t] += sred[t + s];
        __syncthreads();
    }
    if (t == 0) {
        int bid = (blockIdx.z * gridDim.y + blockIdx.y) * gridDim.x + blockIdx.x;
        g_part[bid] = sred[0];
    }
}

// ==== K3: fixed-order final sum ==============================================
__global__ void k_final(float* __restrict__ out, int nblk) {
    __shared__ float sred[256];
    float s = 0.f;
    for (int i = threadIdx.x; i < nblk; i += 256) s += g_part[i];
    sred[threadIdx.x] = s;
    __syncthreads();
    for (int st = 128; st > 0; st >>= 1) {
        if (threadIdx.x < st) sred[threadIdx.x] += sred[threadIdx.x + st];
        __syncthreads();
    }
    if (threadIdx.x == 0) out[0] = sred[0];
}

extern "C" void kernel_launch(void* const* d_in, const int* in_sizes, int n_in,
                              void* d_out, int out_size) {
    const float* preds = (const float*)d_in[0];
    const float* gts   = (const float*)d_in[1];
    float* out = (float*)d_out;
    const int B = in_sizes[0] / (3 * NPTS);  // 8 here

    k_prep<<<2 * B, 256>>>(preds, gts, B);
    k_nop<<<1, 32>>>();
    k_nop<<<1, 32>>>();
    dim3 grid(NPTS / QT, B, 2);              // (32, 8, 2) = 512 blocks
    k_query<<<grid, QT>>>(B);                // <- 4th launch: gets the ncu profile
    k_final<<<1, 256>>>(out, (NPTS / QT) * B * 2);
}